// round 1
// baseline (speedup 1.0000x reference)
#include <cuda_runtime.h>
#include <math.h>

#define NN   50000
#define FIN  512
#define HC1  128
#define H1   8
#define C1   16
#define NC   40
#define EE   800000
#define ETOT (EE + NN)   /* 850000 edges incl. self-loops */
#define NEG  0.2f

// ---------------- scratch (static device globals; no allocation) -------------
__device__ float g_h1  [(size_t)NN * HC1];   // 25.6 MB  x@W1
__device__ float g_out1[(size_t)NN * HC1];   // 25.6 MB  elu(gat1)
__device__ float g_a1s [(size_t)NN * H1];
__device__ float g_a1d [(size_t)NN * H1];
__device__ float g_h2  [(size_t)NN * NC];    // 8 MB
__device__ float g_a2s [NN];
__device__ float g_a2d [NN];
__device__ float g_ex1 [(size_t)ETOT * H1];  // 27.2 MB softmax numerators L1
__device__ float g_ex2 [ETOT];               // 3.4 MB  softmax numerators L2
__device__ int   g_deg [NN];
__device__ int   g_rowptr[NN + 1];
__device__ int   g_wp  [NN];
__device__ int   g_col [ETOT];
__device__ int   g_is32;

// ---------------- edge-index dtype handling ----------------------------------
__device__ __forceinline__ int ld_node(const void* ei, int which, int e, int is32) {
    if (is32) return ((const int*)ei)[which * EE + e];
    return (int)(((const long long*)ei)[which * EE + e]);
}

__global__ void k_init() {
    int i = blockIdx.x * blockDim.x + threadIdx.x;
    if (i < NN) g_deg[i] = 0;
    if (i == 0) g_is32 = 0;
}

// If the buffer is actually int32, reading it as int64 combines pairs of
// values < 50000 into numbers >= 2^32 almost surely -> flag.
__global__ void k_detect(const long long* ei) {
    int i = blockIdx.x * blockDim.x + threadIdx.x;
    if (i >= EE) return;
    long long v = ei[i];
    if (v < 0 || v >= NN) atomicOr(&g_is32, 1);
}

__global__ void k_degree(const void* ei) {
    int e = blockIdx.x * blockDim.x + threadIdx.x;
    if (e >= ETOT) return;
    int is32 = g_is32;
    int dst = (e < EE) ? ld_node(ei, 1, e, is32) : (e - EE);
    atomicAdd(&g_deg[dst], 1);
}

__global__ void k_scan() {
    __shared__ int sh[1024];
    const int CH = (NN + 1023) / 1024;   // 49
    int t = threadIdx.x;
    int start = t * CH;
    int end   = start + CH; if (end > NN) end = NN;
    int s = 0;
    for (int i = start; i < end; i++) s += g_deg[i];
    sh[t] = s;
    __syncthreads();
    for (int off = 1; off < 1024; off <<= 1) {
        int v = 0;
        if (t >= off) v = sh[t - off];
        __syncthreads();
        sh[t] += v;
        __syncthreads();
    }
    int run = sh[t] - s;   // exclusive prefix
    for (int i = start; i < end; i++) {
        g_rowptr[i] = run;
        g_wp[i]     = run;
        run += g_deg[i];
    }
    if (t == 0) g_rowptr[NN] = ETOT;
}

__global__ void k_scatter(const void* ei) {
    int e = blockIdx.x * blockDim.x + threadIdx.x;
    if (e >= ETOT) return;
    int is32 = g_is32;
    int src, dst;
    if (e < EE) { src = ld_node(ei, 0, e, is32); dst = ld_node(ei, 1, e, is32); }
    else        { src = e - EE; dst = src; }
    int pos = atomicAdd(&g_wp[dst], 1);
    g_col[pos] = src;
}

// ---------------- GEMM1: h1[N,128] = x[N,512] @ W1[512,128] -------------------
// BM=64, BN=128, BK=32, 256 threads, per-thread 4x8 micro-tile.
__global__ void k_gemm1(const float* __restrict__ x, const float* __restrict__ W1) {
    __shared__ float sx[64][33];
    __shared__ float sw[32][128];
    int bm  = blockIdx.x * 64;
    int tid = threadIdx.x;
    int tx = tid & 15, ty = tid >> 4;
    float acc[4][8];
#pragma unroll
    for (int i = 0; i < 4; i++)
#pragma unroll
        for (int j = 0; j < 8; j++) acc[i][j] = 0.f;

    for (int k0 = 0; k0 < FIN; k0 += 32) {
        // x tile: 64 rows x 32 k
        {
            int r = tid >> 2;
            int c = (tid & 3) * 8;
            int grow = bm + r;
            float4 v0 = make_float4(0, 0, 0, 0), v1 = make_float4(0, 0, 0, 0);
            if (grow < NN) {
                const float4* p = (const float4*)(x + (size_t)grow * FIN + k0 + c);
                v0 = p[0]; v1 = p[1];
            }
            sx[r][c + 0] = v0.x; sx[r][c + 1] = v0.y; sx[r][c + 2] = v0.z; sx[r][c + 3] = v0.w;
            sx[r][c + 4] = v1.x; sx[r][c + 5] = v1.y; sx[r][c + 6] = v1.z; sx[r][c + 7] = v1.w;
        }
        // W tile: 32 k x 128 cols (1024 float4 / 256 thr = 4 each)
#pragma unroll
        for (int it = 0; it < 4; it++) {
            int idx = tid + it * 256;
            int rw = idx >> 5;
            int cw = (idx & 31) * 4;
            *(float4*)&sw[rw][cw] = *(const float4*)(W1 + (size_t)(k0 + rw) * HC1 + cw);
        }
        __syncthreads();
#pragma unroll 8
        for (int k = 0; k < 32; k++) {
            float xr[4];
#pragma unroll
            for (int i = 0; i < 4; i++) xr[i] = sx[ty * 4 + i][k];
            float4 w0 = *(float4*)&sw[k][tx * 8];
            float4 w1 = *(float4*)&sw[k][tx * 8 + 4];
#pragma unroll
            for (int i = 0; i < 4; i++) {
                acc[i][0] += xr[i] * w0.x; acc[i][1] += xr[i] * w0.y;
                acc[i][2] += xr[i] * w0.z; acc[i][3] += xr[i] * w0.w;
                acc[i][4] += xr[i] * w1.x; acc[i][5] += xr[i] * w1.y;
                acc[i][6] += xr[i] * w1.z; acc[i][7] += xr[i] * w1.w;
            }
        }
        __syncthreads();
    }
#pragma unroll
    for (int i = 0; i < 4; i++) {
        int grow = bm + ty * 4 + i;
        if (grow < NN) {
            float* o = g_h1 + (size_t)grow * HC1 + tx * 8;
            *(float4*)o       = make_float4(acc[i][0], acc[i][1], acc[i][2], acc[i][3]);
            *(float4*)(o + 4) = make_float4(acc[i][4], acc[i][5], acc[i][6], acc[i][7]);
        }
    }
}

// ---------------- per-node attention dots, layer 1 ----------------------------
__global__ void k_attn1(const float* __restrict__ as, const float* __restrict__ ad) {
    int w = (blockIdx.x * blockDim.x + threadIdx.x) >> 5;
    int lane = threadIdx.x & 31;
    if (w >= NN) return;
#pragma unroll
    for (int j = 0; j < 4; j++) {
        float v  = g_h1[(size_t)w * HC1 + j * 32 + lane];
        float ps = v * as[j * 32 + lane];
        float pd = v * ad[j * 32 + lane];
#pragma unroll
        for (int off = 8; off >= 1; off >>= 1) {
            ps += __shfl_xor_sync(0xffffffffu, ps, off);
            pd += __shfl_xor_sync(0xffffffffu, pd, off);
        }
        if ((lane & 15) == 0) {
            int h = j * 2 + (lane >> 4);
            g_a1s[w * H1 + h] = ps;
            g_a1d[w * H1 + h] = pd;
        }
    }
}

// ---------------- layer-1 edge softmax + aggregation + ELU (warp per dst) -----
__global__ void k_edge1(const float* __restrict__ b1) {
    int wib  = threadIdx.x >> 5;
    int dst  = (blockIdx.x * blockDim.x + threadIdx.x) >> 5;
    int lane = threadIdx.x & 31;
    __shared__ float s_inv[8][8];
    if (dst >= NN) return;
    int row = g_rowptr[dst];
    int deg = g_rowptr[dst + 1] - row;

    float ad[8];
    {
        const float4* p = (const float4*)(g_a1d + (size_t)dst * H1);
        float4 A = p[0], B = p[1];
        ad[0] = A.x; ad[1] = A.y; ad[2] = A.z; ad[3] = A.w;
        ad[4] = B.x; ad[5] = B.y; ad[6] = B.z; ad[7] = B.w;
    }
    float mx[8];
#pragma unroll
    for (int h = 0; h < 8; h++) mx[h] = -1e30f;

    for (int j = lane; j < deg; j += 32) {
        int s = g_col[row + j];
        const float4* p = (const float4*)(g_a1s + (size_t)s * H1);
        float4 A = p[0], B = p[1];
        float ev[8] = {A.x + ad[0], A.y + ad[1], A.z + ad[2], A.w + ad[3],
                       B.x + ad[4], B.y + ad[5], B.z + ad[6], B.w + ad[7]};
#pragma unroll
        for (int h = 0; h < 8; h++) {
            float e = ev[h]; e = e > 0.f ? e : NEG * e;
            mx[h] = fmaxf(mx[h], e);
        }
    }
#pragma unroll
    for (int h = 0; h < 8; h++)
#pragma unroll
        for (int off = 16; off >= 1; off >>= 1)
            mx[h] = fmaxf(mx[h], __shfl_xor_sync(0xffffffffu, mx[h], off));

    float sm[8];
#pragma unroll
    for (int h = 0; h < 8; h++) sm[h] = 0.f;
    for (int j = lane; j < deg; j += 32) {
        int s = g_col[row + j];
        const float4* p = (const float4*)(g_a1s + (size_t)s * H1);
        float4 A = p[0], B = p[1];
        float ev[8] = {A.x + ad[0], A.y + ad[1], A.z + ad[2], A.w + ad[3],
                       B.x + ad[4], B.y + ad[5], B.z + ad[6], B.w + ad[7]};
#pragma unroll
        for (int h = 0; h < 8; h++) {
            float e = ev[h]; e = e > 0.f ? e : NEG * e;
            float ex = __expf(e - mx[h]);
            sm[h] += ex;
            g_ex1[(size_t)(row + j) * H1 + h] = ex;
        }
    }
#pragma unroll
    for (int h = 0; h < 8; h++)
#pragma unroll
        for (int off = 16; off >= 1; off >>= 1)
            sm[h] += __shfl_xor_sync(0xffffffffu, sm[h], off);
    if (lane == 0) {
#pragma unroll
        for (int h = 0; h < 8; h++) s_inv[wib][h] = 1.0f / (sm[h] + 1e-16f);
    }
    __syncwarp();
    float inv = s_inv[wib][lane >> 2];   // lane covers channels lane*4..+3, head = lane/4

    float4 acc = make_float4(0, 0, 0, 0);
    for (int j = 0; j < deg; j++) {
        int s = g_col[row + j];
        float al = g_ex1[(size_t)(row + j) * H1 + (lane >> 2)] * inv;
        float4 v = *(const float4*)(g_h1 + (size_t)s * HC1 + lane * 4);
        acc.x += v.x * al; acc.y += v.y * al; acc.z += v.z * al; acc.w += v.w * al;
    }
    int c = lane * 4;
    float4 b = *(const float4*)(b1 + c);
    float o0 = acc.x + b.x, o1 = acc.y + b.y, o2 = acc.z + b.z, o3 = acc.w + b.w;
    o0 = o0 > 0.f ? o0 : expm1f(o0);
    o1 = o1 > 0.f ? o1 : expm1f(o1);
    o2 = o2 > 0.f ? o2 : expm1f(o2);
    o3 = o3 > 0.f ? o3 : expm1f(o3);
    *(float4*)(g_out1 + (size_t)dst * HC1 + c) = make_float4(o0, o1, o2, o3);
}

// ---------------- GEMM2: h2[N,40] = out1[N,128] @ W2[128,40] -----------------
// BM=64, 128 threads, per-thread 4 rows x 5 cols (col stride 8), K chunked by 64.
__global__ void k_gemm2(const float* __restrict__ W2) {
    __shared__ float shh[64][65];
    __shared__ float sww[64][NC];
    int bm  = blockIdx.x * 64;
    int tid = threadIdx.x;               // 128 threads
    int rg = tid >> 3, cg = tid & 7;
    float acc[4][5];
#pragma unroll
    for (int i = 0; i < 4; i++)
#pragma unroll
        for (int j = 0; j < 5; j++) acc[i][j] = 0.f;

    for (int k0 = 0; k0 < HC1; k0 += 64) {
#pragma unroll
        for (int it = 0; it < 8; it++) {
            int idx = tid + it * 128;    // float4 index over 64x64 tile
            int r = idx >> 4;
            int kk = (idx & 15) * 4;
            int grow = bm + r;
            float4 v = make_float4(0, 0, 0, 0);
            if (grow < NN) v = *(const float4*)(g_out1 + (size_t)grow * HC1 + k0 + kk);
            shh[r][kk] = v.x; shh[r][kk + 1] = v.y; shh[r][kk + 2] = v.z; shh[r][kk + 3] = v.w;
        }
#pragma unroll
        for (int it = 0; it < 20; it++) {
            int idx = tid + it * 128;    // 64x40 = 2560
            int rw = idx / NC, cw = idx % NC;
            sww[rw][cw] = W2[(size_t)(k0 + rw) * NC + cw];
        }
        __syncthreads();
#pragma unroll 8
        for (int k = 0; k < 64; k++) {
            float hr[4], wr[5];
#pragma unroll
            for (int i = 0; i < 4; i++) hr[i] = shh[rg * 4 + i][k];
#pragma unroll
            for (int j = 0; j < 5; j++) wr[j] = sww[k][cg + 8 * j];
#pragma unroll
            for (int i = 0; i < 4; i++)
#pragma unroll
                for (int j = 0; j < 5; j++) acc[i][j] += hr[i] * wr[j];
        }
        __syncthreads();
    }
#pragma unroll
    for (int i = 0; i < 4; i++) {
        int grow = bm + rg * 4 + i;
        if (grow < NN) {
#pragma unroll
            for (int j = 0; j < 5; j++)
                g_h2[(size_t)grow * NC + cg + 8 * j] = acc[i][j];
        }
    }
}

// ---------------- per-node attention dots, layer 2 ----------------------------
__global__ void k_attn2(const float* __restrict__ as2, const float* __restrict__ ad2) {
    int w = (blockIdx.x * blockDim.x + threadIdx.x) >> 5;
    int lane = threadIdx.x & 31;
    if (w >= NN) return;
    float v0 = g_h2[(size_t)w * NC + lane];
    float s = v0 * as2[lane];
    float d = v0 * ad2[lane];
    if (lane < 8) {
        float v1 = g_h2[(size_t)w * NC + 32 + lane];
        s += v1 * as2[32 + lane];
        d += v1 * ad2[32 + lane];
    }
#pragma unroll
    for (int off = 16; off >= 1; off >>= 1) {
        s += __shfl_xor_sync(0xffffffffu, s, off);
        d += __shfl_xor_sync(0xffffffffu, d, off);
    }
    if (lane == 0) { g_a2s[w] = s; g_a2d[w] = d; }
}

// ---------------- layer-2 edge softmax + aggregation + log_softmax ------------
__global__ void k_edge2(const float* __restrict__ b2, float* __restrict__ out) {
    int dst  = (blockIdx.x * blockDim.x + threadIdx.x) >> 5;
    int lane = threadIdx.x & 31;
    if (dst >= NN) return;
    int row = g_rowptr[dst];
    int deg = g_rowptr[dst + 1] - row;
    float adv = g_a2d[dst];

    float mx = -1e30f;
    for (int j = lane; j < deg; j += 32) {
        int s = g_col[row + j];
        float e = g_a2s[s] + adv; e = e > 0.f ? e : NEG * e;
        mx = fmaxf(mx, e);
    }
#pragma unroll
    for (int off = 16; off >= 1; off >>= 1)
        mx = fmaxf(mx, __shfl_xor_sync(0xffffffffu, mx, off));

    float sm = 0.f;
    for (int j = lane; j < deg; j += 32) {
        int s = g_col[row + j];
        float e = g_a2s[s] + adv; e = e > 0.f ? e : NEG * e;
        float ex = __expf(e - mx);
        sm += ex;
        g_ex2[row + j] = ex;
    }
#pragma unroll
    for (int off = 16; off >= 1; off >>= 1)
        sm += __shfl_xor_sync(0xffffffffu, sm, off);
    float inv = 1.0f / (sm + 1e-16f);

    float acc0 = 0.f, acc1 = 0.f;
    for (int j = 0; j < deg; j++) {
        int s = g_col[row + j];
        float al = g_ex2[row + j] * inv;
        acc0 += g_h2[(size_t)s * NC + lane] * al;
        if (lane < 8) acc1 += g_h2[(size_t)s * NC + 32 + lane] * al;
    }
    acc0 += b2[lane];
    if (lane < 8) acc1 += b2[32 + lane];

    float vm = (lane < 8) ? fmaxf(acc0, acc1) : acc0;
#pragma unroll
    for (int off = 16; off >= 1; off >>= 1)
        vm = fmaxf(vm, __shfl_xor_sync(0xffffffffu, vm, off));
    float se = __expf(acc0 - vm) + ((lane < 8) ? __expf(acc1 - vm) : 0.f);
#pragma unroll
    for (int off = 16; off >= 1; off >>= 1)
        se += __shfl_xor_sync(0xffffffffu, se, off);
    float lse = vm + __logf(se);

    out[(size_t)dst * NC + lane] = acc0 - lse;
    if (lane < 8) out[(size_t)dst * NC + 32 + lane] = acc1 - lse;
}

// ---------------- host ---------------------------------------------------------
extern "C" void kernel_launch(void* const* d_in, const int* in_sizes, int n_in,
                              void* d_out, int out_size) {
    const float* x   = (const float*)d_in[0];
    const void*  ei  = d_in[1];
    const float* W1  = (const float*)d_in[2];
    const float* as1 = (const float*)d_in[3];
    const float* ad1 = (const float*)d_in[4];
    const float* b1  = (const float*)d_in[5];
    const float* W2  = (const float*)d_in[6];
    const float* as2 = (const float*)d_in[7];
    const float* ad2 = (const float*)d_in[8];
    const float* b2  = (const float*)d_in[9];
    float* out = (float*)d_out;

    k_init   <<<(NN + 255) / 256, 256>>>();
    k_detect <<<(EE + 255) / 256, 256>>>((const long long*)ei);
    k_degree <<<(ETOT + 255) / 256, 256>>>(ei);
    k_scan   <<<1, 1024>>>();
    k_scatter<<<(ETOT + 255) / 256, 256>>>(ei);

    k_gemm1  <<<(NN + 63) / 64, 256>>>(x, W1);
    k_attn1  <<<(NN * 32 + 255) / 256, 256>>>(as1, ad1);
    k_edge1  <<<(NN * 32 + 255) / 256, 256>>>(b1);

    k_gemm2  <<<(NN + 63) / 64, 128>>>(W2);
    k_attn2  <<<(NN * 32 + 255) / 256, 256>>>(as2, ad2);
    k_edge2  <<<(NN * 32 + 255) / 256, 256>>>(b2, out);
}

// round 2
// speedup vs baseline: 1.4459x; 1.4459x over previous
#include <cuda_runtime.h>
#include <math.h>

#define NN   50000
#define FIN  512
#define HC1  128
#define H1   8
#define C1   16
#define NC   40
#define EE   800000
#define ETOT (EE + NN)   /* 850000 edges incl. self-loops */
#define NEG  0.2f
#define NB   ((NN + 255) / 256)   /* 196 scan blocks */

// ---------------- scratch (static device globals; no allocation) -------------
__device__ float g_h1  [(size_t)NN * HC1];   // 25.6 MB  x@W1
__device__ float g_out1[(size_t)NN * HC1];   // 25.6 MB  elu(gat1)
__device__ float g_a1s [(size_t)NN * H1];
__device__ float g_a1d [(size_t)NN * H1];
__device__ float g_h2  [(size_t)NN * NC];    // 8 MB
__device__ float g_a2s [NN];
__device__ float g_a2d [NN];
__device__ float g_ex1 [(size_t)ETOT * H1];  // 27.2 MB softmax numerators L1
__device__ float g_ex2 [ETOT];               // 3.4 MB  softmax numerators L2
__device__ int   g_deg [NN];
__device__ int   g_rowptr[NN + 1];
__device__ int   g_wp  [NN];
__device__ int   g_col [ETOT];
__device__ int   g_is32;
__device__ int   g_bsum[256];
__device__ int   g_boff[256];

// ---------------- f32x2 packed math helpers -----------------------------------
__device__ __forceinline__ unsigned long long ffma2(unsigned long long a,
                                                    unsigned long long b,
                                                    unsigned long long c) {
    unsigned long long d;
    asm("fma.rn.f32x2 %0, %1, %2, %3;" : "=l"(d) : "l"(a), "l"(b), "l"(c));
    return d;
}
__device__ __forceinline__ unsigned long long pack2(float lo, float hi) {
    unsigned long long d;
    asm("mov.b64 %0, {%1, %2};" : "=l"(d) : "f"(lo), "f"(hi));
    return d;
}
__device__ __forceinline__ void unpack2(unsigned long long v, float& lo, float& hi) {
    asm("mov.b64 {%0, %1}, %2;" : "=f"(lo), "=f"(hi) : "l"(v));
}

// ---------------- edge-index dtype handling ----------------------------------
__device__ __forceinline__ int ld_node(const void* ei, int which, int e, int is32) {
    if (is32) return ((const int*)ei)[which * EE + e];
    return (int)(((const long long*)ei)[which * EE + e]);
}

__global__ void k_init() {
    int i = blockIdx.x * blockDim.x + threadIdx.x;
    if (i < NN) g_deg[i] = 0;
    if (i == 0) g_is32 = 0;
}

// If the buffer is actually int32, reading it as int64 combines pairs of
// values < 50000 into numbers >= 2^32 almost surely -> flag.
__global__ void k_detect(const long long* ei) {
    int i = blockIdx.x * blockDim.x + threadIdx.x;
    if (i >= EE) return;
    long long v = ei[i];
    if (v < 0 || v >= NN) atomicOr(&g_is32, 1);
}

__global__ void k_degree(const void* ei) {
    int e = blockIdx.x * blockDim.x + threadIdx.x;
    if (e >= ETOT) return;
    int is32 = g_is32;
    int dst = (e < EE) ? ld_node(ei, 1, e, is32) : (e - EE);
    atomicAdd(&g_deg[dst], 1);
}

// ---- multi-block exclusive scan of g_deg -> g_rowptr / g_wp ------------------
__global__ void k_scan_blk() {
    __shared__ int ws[8];
    int t = threadIdx.x, i = blockIdx.x * 256 + t;
    int lane = t & 31, wid = t >> 5;
    int v = (i < NN) ? g_deg[i] : 0;
#pragma unroll
    for (int off = 16; off >= 1; off >>= 1) v += __shfl_xor_sync(0xffffffffu, v, off);
    if (lane == 0) ws[wid] = v;
    __syncthreads();
    if (t == 0) {
        int s = 0;
#pragma unroll
        for (int j = 0; j < 8; j++) s += ws[j];
        g_bsum[blockIdx.x] = s;
    }
}

__global__ void k_scan_top() {
    __shared__ int sh[256];
    int t = threadIdx.x;
    int v = (t < NB) ? g_bsum[t] : 0;
    sh[t] = v;
    __syncthreads();
#pragma unroll
    for (int off = 1; off < 256; off <<= 1) {
        int u = (t >= off) ? sh[t - off] : 0;
        __syncthreads();
        sh[t] += u;
        __syncthreads();
    }
    g_boff[t] = sh[t] - v;   // exclusive
    if (t == 0) g_rowptr[NN] = ETOT;
}

__global__ void k_scan_fin() {
    __shared__ int wsum[8];
    int t = threadIdx.x, i = blockIdx.x * 256 + t;
    int lane = t & 31, wid = t >> 5;
    int d = (i < NN) ? g_deg[i] : 0;
    int incl = d;
#pragma unroll
    for (int off = 1; off < 32; off <<= 1) {
        int n = __shfl_up_sync(0xffffffffu, incl, off);
        if (lane >= off) incl += n;
    }
    if (lane == 31) wsum[wid] = incl;
    __syncthreads();
    if (t == 0) {
        int run = 0;
#pragma unroll
        for (int j = 0; j < 8; j++) { int tmp = wsum[j]; wsum[j] = run; run += tmp; }
    }
    __syncthreads();
    int excl = g_boff[blockIdx.x] + wsum[wid] + incl - d;
    if (i < NN) { g_rowptr[i] = excl; g_wp[i] = excl; }
}

__global__ void k_scatter(const void* ei) {
    int e = blockIdx.x * blockDim.x + threadIdx.x;
    if (e >= ETOT) return;
    int is32 = g_is32;
    int src, dst;
    if (e < EE) { src = ld_node(ei, 0, e, is32); dst = ld_node(ei, 1, e, is32); }
    else        { src = e - EE; dst = src; }
    int pos = atomicAdd(&g_wp[dst], 1);
    g_col[pos] = src;
}

// ---------------- GEMM1: h1[N,128] = x[N,512] @ W1[512,128] -------------------
// BM=128, BN=128, BK=32, 256 threads, per-thread 8x8 micro-tile, f32x2 packed.
// x tile stored TRANSPOSED in smem so the 8 row-values per k are 2x LDS.128.
__global__ __launch_bounds__(256) void k_gemm1(const float* __restrict__ x,
                                               const float* __restrict__ W1) {
    __shared__ float sxT[32][132];    // [k][row], row pitch 132 (16B-aligned)
    __shared__ float sw [32][128];    // [k][col]
    int bm  = blockIdx.x * 128;
    int tid = threadIdx.x;
    int tx = tid & 15;                // col group (8 cols each)
    int ty = tid >> 4;                // row group (8 rows each)

    unsigned long long acc[8][4];     // 8 rows x 4 col-pairs
#pragma unroll
    for (int i = 0; i < 8; i++)
#pragma unroll
        for (int j = 0; j < 4; j++) acc[i][j] = 0ULL;

    int ldr  = tid >> 1;              // row this thread loads (2 threads/row)
    int ldc0 = (tid & 1) * 16;        // k-offset within BK
    int lgrow = bm + ldr;

    for (int k0 = 0; k0 < FIN; k0 += 32) {
        // x tile (transposed write): 128 rows x 32 k
        {
            float4 v0 = make_float4(0,0,0,0), v1 = v0, v2 = v0, v3 = v0;
            if (lgrow < NN) {
                const float4* p = (const float4*)(x + (size_t)lgrow * FIN + k0 + ldc0);
                v0 = p[0]; v1 = p[1]; v2 = p[2]; v3 = p[3];
            }
            sxT[ldc0 +  0][ldr] = v0.x; sxT[ldc0 +  1][ldr] = v0.y;
            sxT[ldc0 +  2][ldr] = v0.z; sxT[ldc0 +  3][ldr] = v0.w;
            sxT[ldc0 +  4][ldr] = v1.x; sxT[ldc0 +  5][ldr] = v1.y;
            sxT[ldc0 +  6][ldr] = v1.z; sxT[ldc0 +  7][ldr] = v1.w;
            sxT[ldc0 +  8][ldr] = v2.x; sxT[ldc0 +  9][ldr] = v2.y;
            sxT[ldc0 + 10][ldr] = v2.z; sxT[ldc0 + 11][ldr] = v2.w;
            sxT[ldc0 + 12][ldr] = v3.x; sxT[ldc0 + 13][ldr] = v3.y;
            sxT[ldc0 + 14][ldr] = v3.z; sxT[ldc0 + 15][ldr] = v3.w;
        }
        // W tile: 32 k x 128 cols
#pragma unroll
        for (int it = 0; it < 4; it++) {
            int idx = tid + it * 256;
            int rw = idx >> 5;
            int cw = (idx & 31) * 4;
            *(float4*)&sw[rw][cw] = *(const float4*)(W1 + (size_t)(k0 + rw) * HC1 + cw);
        }
        __syncthreads();

#pragma unroll
        for (int k = 0; k < 32; k++) {
            float4 xa = *(float4*)&sxT[k][ty * 8];
            float4 xb = *(float4*)&sxT[k][ty * 8 + 4];
            unsigned long long xp[8];
            xp[0] = pack2(xa.x, xa.x); xp[1] = pack2(xa.y, xa.y);
            xp[2] = pack2(xa.z, xa.z); xp[3] = pack2(xa.w, xa.w);
            xp[4] = pack2(xb.x, xb.x); xp[5] = pack2(xb.y, xb.y);
            xp[6] = pack2(xb.z, xb.z); xp[7] = pack2(xb.w, xb.w);
            unsigned long long wp_[4];
#pragma unroll
            for (int j = 0; j < 4; j++)
                wp_[j] = *(const unsigned long long*)&sw[k][tx * 8 + 2 * j];
#pragma unroll
            for (int i = 0; i < 8; i++)
#pragma unroll
                for (int j = 0; j < 4; j++)
                    acc[i][j] = ffma2(xp[i], wp_[j], acc[i][j]);
        }
        __syncthreads();
    }

#pragma unroll
    for (int i = 0; i < 8; i++) {
        int grow = bm + ty * 8 + i;
        if (grow < NN) {
            float o[8];
#pragma unroll
            for (int j = 0; j < 4; j++) unpack2(acc[i][j], o[2*j], o[2*j+1]);
            float* p = g_h1 + (size_t)grow * HC1 + tx * 8;
            *(float4*)p       = make_float4(o[0], o[1], o[2], o[3]);
            *(float4*)(p + 4) = make_float4(o[4], o[5], o[6], o[7]);
        }
    }
}

// ---------------- per-node attention dots, layer 1 ----------------------------
__global__ void k_attn1(const float* __restrict__ as, const float* __restrict__ ad) {
    int w = (blockIdx.x * blockDim.x + threadIdx.x) >> 5;
    int lane = threadIdx.x & 31;
    if (w >= NN) return;
#pragma unroll
    for (int j = 0; j < 4; j++) {
        float v  = g_h1[(size_t)w * HC1 + j * 32 + lane];
        float ps = v * as[j * 32 + lane];
        float pd = v * ad[j * 32 + lane];
#pragma unroll
        for (int off = 8; off >= 1; off >>= 1) {
            ps += __shfl_xor_sync(0xffffffffu, ps, off);
            pd += __shfl_xor_sync(0xffffffffu, pd, off);
        }
        if ((lane & 15) == 0) {
            int h = j * 2 + (lane >> 4);
            g_a1s[w * H1 + h] = ps;
            g_a1d[w * H1 + h] = pd;
        }
    }
}

// ---------------- layer-1 edge softmax + aggregation + ELU (warp per dst) -----
__global__ void k_edge1(const float* __restrict__ b1) {
    int wib  = threadIdx.x >> 5;
    int dst  = (blockIdx.x * blockDim.x + threadIdx.x) >> 5;
    int lane = threadIdx.x & 31;
    __shared__ float s_inv[8][8];
    if (dst >= NN) return;
    int row = g_rowptr[dst];
    int deg = g_rowptr[dst + 1] - row;

    float ad[8];
    {
        const float4* p = (const float4*)(g_a1d + (size_t)dst * H1);
        float4 A = p[0], B = p[1];
        ad[0] = A.x; ad[1] = A.y; ad[2] = A.z; ad[3] = A.w;
        ad[4] = B.x; ad[5] = B.y; ad[6] = B.z; ad[7] = B.w;
    }
    float mx[8];
#pragma unroll
    for (int h = 0; h < 8; h++) mx[h] = -1e30f;

    for (int j = lane; j < deg; j += 32) {
        int s = g_col[row + j];
        const float4* p = (const float4*)(g_a1s + (size_t)s * H1);
        float4 A = p[0], B = p[1];
        float ev[8] = {A.x + ad[0], A.y + ad[1], A.z + ad[2], A.w + ad[3],
                       B.x + ad[4], B.y + ad[5], B.z + ad[6], B.w + ad[7]};
#pragma unroll
        for (int h = 0; h < 8; h++) {
            float e = ev[h]; e = e > 0.f ? e : NEG * e;
            mx[h] = fmaxf(mx[h], e);
        }
    }
#pragma unroll
    for (int h = 0; h < 8; h++)
#pragma unroll
        for (int off = 16; off >= 1; off >>= 1)
            mx[h] = fmaxf(mx[h], __shfl_xor_sync(0xffffffffu, mx[h], off));

    float sm[8];
#pragma unroll
    for (int h = 0; h < 8; h++) sm[h] = 0.f;
    for (int j = lane; j < deg; j += 32) {
        int s = g_col[row + j];
        const float4* p = (const float4*)(g_a1s + (size_t)s * H1);
        float4 A = p[0], B = p[1];
        float ev[8] = {A.x + ad[0], A.y + ad[1], A.z + ad[2], A.w + ad[3],
                       B.x + ad[4], B.y + ad[5], B.z + ad[6], B.w + ad[7]};
#pragma unroll
        for (int h = 0; h < 8; h++) {
            float e = ev[h]; e = e > 0.f ? e : NEG * e;
            float ex = __expf(e - mx[h]);
            sm[h] += ex;
            g_ex1[(size_t)(row + j) * H1 + h] = ex;
        }
    }
#pragma unroll
    for (int h = 0; h < 8; h++)
#pragma unroll
        for (int off = 16; off >= 1; off >>= 1)
            sm[h] += __shfl_xor_sync(0xffffffffu, sm[h], off);
    if (lane == 0) {
#pragma unroll
        for (int h = 0; h < 8; h++) s_inv[wib][h] = 1.0f / (sm[h] + 1e-16f);
    }
    __syncwarp();
    float inv = s_inv[wib][lane >> 2];   // lane covers channels lane*4..+3, head = lane/4

    float4 acc = make_float4(0, 0, 0, 0);
    for (int j = 0; j < deg; j++) {
        int s = g_col[row + j];
        float al = g_ex1[(size_t)(row + j) * H1 + (lane >> 2)] * inv;
        float4 v = *(const float4*)(g_h1 + (size_t)s * HC1 + lane * 4);
        acc.x += v.x * al; acc.y += v.y * al; acc.z += v.z * al; acc.w += v.w * al;
    }
    int c = lane * 4;
    float4 b = *(const float4*)(b1 + c);
    float o0 = acc.x + b.x, o1 = acc.y + b.y, o2 = acc.z + b.z, o3 = acc.w + b.w;
    o0 = o0 > 0.f ? o0 : expm1f(o0);
    o1 = o1 > 0.f ? o1 : expm1f(o1);
    o2 = o2 > 0.f ? o2 : expm1f(o2);
    o3 = o3 > 0.f ? o3 : expm1f(o3);
    *(float4*)(g_out1 + (size_t)dst * HC1 + c) = make_float4(o0, o1, o2, o3);
}

// ---------------- GEMM2: h2[N,40] = out1[N,128] @ W2[128,40] -----------------
__global__ void k_gemm2(const float* __restrict__ W2) {
    __shared__ float shh[64][65];
    __shared__ float sww[64][NC];
    int bm  = blockIdx.x * 64;
    int tid = threadIdx.x;               // 128 threads
    int rg = tid >> 3, cg = tid & 7;
    float acc[4][5];
#pragma unroll
    for (int i = 0; i < 4; i++)
#pragma unroll
        for (int j = 0; j < 5; j++) acc[i][j] = 0.f;

    for (int k0 = 0; k0 < HC1; k0 += 64) {
#pragma unroll
        for (int it = 0; it < 8; it++) {
            int idx = tid + it * 128;    // float4 index over 64x64 tile
            int r = idx >> 4;
            int kk = (idx & 15) * 4;
            int grow = bm + r;
            float4 v = make_float4(0, 0, 0, 0);
            if (grow < NN) v = *(const float4*)(g_out1 + (size_t)grow * HC1 + k0 + kk);
            shh[r][kk] = v.x; shh[r][kk + 1] = v.y; shh[r][kk + 2] = v.z; shh[r][kk + 3] = v.w;
        }
#pragma unroll
        for (int it = 0; it < 20; it++) {
            int idx = tid + it * 128;    // 64x40 = 2560
            int rw = idx / NC, cw = idx % NC;
            sww[rw][cw] = W2[(size_t)(k0 + rw) * NC + cw];
        }
        __syncthreads();
#pragma unroll 8
        for (int k = 0; k < 64; k++) {
            float hr[4], wr[5];
#pragma unroll
            for (int i = 0; i < 4; i++) hr[i] = shh[rg * 4 + i][k];
#pragma unroll
            for (int j = 0; j < 5; j++) wr[j] = sww[k][cg + 8 * j];
#pragma unroll
            for (int i = 0; i < 4; i++)
#pragma unroll
                for (int j = 0; j < 5; j++) acc[i][j] += hr[i] * wr[j];
        }
        __syncthreads();
    }
#pragma unroll
    for (int i = 0; i < 4; i++) {
        int grow = bm + rg * 4 + i;
        if (grow < NN) {
#pragma unroll
            for (int j = 0; j < 5; j++)
                g_h2[(size_t)grow * NC + cg + 8 * j] = acc[i][j];
        }
    }
}

// ---------------- per-node attention dots, layer 2 ----------------------------
__global__ void k_attn2(const float* __restrict__ as2, const float* __restrict__ ad2) {
    int w = (blockIdx.x * blockDim.x + threadIdx.x) >> 5;
    int lane = threadIdx.x & 31;
    if (w >= NN) return;
    float v0 = g_h2[(size_t)w * NC + lane];
    float s = v0 * as2[lane];
    float d = v0 * ad2[lane];
    if (lane < 8) {
        float v1 = g_h2[(size_t)w * NC + 32 + lane];
        s += v1 * as2[32 + lane];
        d += v1 * ad2[32 + lane];
    }
#pragma unroll
    for (int off = 16; off >= 1; off >>= 1) {
        s += __shfl_xor_sync(0xffffffffu, s, off);
        d += __shfl_xor_sync(0xffffffffu, d, off);
    }
    if (lane == 0) { g_a2s[w] = s; g_a2d[w] = d; }
}

// ---------------- layer-2 edge softmax + aggregation + log_softmax ------------
__global__ void k_edge2(const float* __restrict__ b2, float* __restrict__ out) {
    int dst  = (blockIdx.x * blockDim.x + threadIdx.x) >> 5;
    int lane = threadIdx.x & 31;
    if (dst >= NN) return;
    int row = g_rowptr[dst];
    int deg = g_rowptr[dst + 1] - row;
    float adv = g_a2d[dst];

    float mx = -1e30f;
    for (int j = lane; j < deg; j += 32) {
        int s = g_col[row + j];
        float e = g_a2s[s] + adv; e = e > 0.f ? e : NEG * e;
        mx = fmaxf(mx, e);
    }
#pragma unroll
    for (int off = 16; off >= 1; off >>= 1)
        mx = fmaxf(mx, __shfl_xor_sync(0xffffffffu, mx, off));

    float sm = 0.f;
    for (int j = lane; j < deg; j += 32) {
        int s = g_col[row + j];
        float e = g_a2s[s] + adv; e = e > 0.f ? e : NEG * e;
        float ex = __expf(e - mx);
        sm += ex;
        g_ex2[row + j] = ex;
    }
#pragma unroll
    for (int off = 16; off >= 1; off >>= 1)
        sm += __shfl_xor_sync(0xffffffffu, sm, off);
    float inv = 1.0f / (sm + 1e-16f);

    float acc0 = 0.f, acc1 = 0.f;
    for (int j = 0; j < deg; j++) {
        int s = g_col[row + j];
        float al = g_ex2[row + j] * inv;
        acc0 += g_h2[(size_t)s * NC + lane] * al;
        if (lane < 8) acc1 += g_h2[(size_t)s * NC + 32 + lane] * al;
    }
    acc0 += b2[lane];
    if (lane < 8) acc1 += b2[32 + lane];

    float vm = (lane < 8) ? fmaxf(acc0, acc1) : acc0;
#pragma unroll
    for (int off = 16; off >= 1; off >>= 1)
        vm = fmaxf(vm, __shfl_xor_sync(0xffffffffu, vm, off));
    float se = __expf(acc0 - vm) + ((lane < 8) ? __expf(acc1 - vm) : 0.f);
#pragma unroll
    for (int off = 16; off >= 1; off >>= 1)
        se += __shfl_xor_sync(0xffffffffu, se, off);
    float lse = vm + __logf(se);

    out[(size_t)dst * NC + lane] = acc0 - lse;
    if (lane < 8) out[(size_t)dst * NC + 32 + lane] = acc1 - lse;
}

// ---------------- host ---------------------------------------------------------
extern "C" void kernel_launch(void* const* d_in, const int* in_sizes, int n_in,
                              void* d_out, int out_size) {
    const float* x   = (const float*)d_in[0];
    const void*  ei  = d_in[1];
    const float* W1  = (const float*)d_in[2];
    const float* as1 = (const float*)d_in[3];
    const float* ad1 = (const float*)d_in[4];
    const float* b1  = (const float*)d_in[5];
    const float* W2  = (const float*)d_in[6];
    const float* as2 = (const float*)d_in[7];
    const float* ad2 = (const float*)d_in[8];
    const float* b2  = (const float*)d_in[9];
    float* out = (float*)d_out;

    k_init    <<<(NN + 255) / 256, 256>>>();
    k_detect  <<<(EE + 255) / 256, 256>>>((const long long*)ei);
    k_degree  <<<(ETOT + 255) / 256, 256>>>(ei);
    k_scan_blk<<<NB, 256>>>();
    k_scan_top<<<1, 256>>>();
    k_scan_fin<<<NB, 256>>>();
    k_scatter <<<(ETOT + 255) / 256, 256>>>(ei);

    k_gemm1   <<<(NN + 127) / 128, 256>>>(x, W1);
    k_attn1   <<<(NN * 32 + 255) / 256, 256>>>(as1, ad1);
    k_edge1   <<<(NN * 32 + 255) / 256, 256>>>(b1);

    k_gemm2   <<<(NN + 63) / 64, 128>>>(W2);
    k_attn2   <<<(NN * 32 + 255) / 256, 256>>>(as2, ad2);
    k_edge2   <<<(NN * 32 + 255) / 256, 256>>>(b2, out);
}